// round 1
// baseline (speedup 1.0000x reference)
#include <cuda_runtime.h>
#include <math_constants.h>

// Prefix-max (cumulative max) along H for x of shape (B=32, C=1, H=1024, W=1024), fp32.
// Layout: x[((b*H)+h)*W + w]. 32768 independent columns (b,w), scan length 1024.
//
// Strategy: each block handles 32 consecutive columns x full H.
//   blockDim = 1024: thread t -> col_in_tile = t & 31, chunk = t >> 5 (32 chunks of 32 rows).
//   Each thread: 32 coalesced loads into registers, local prefix-max,
//   block-level Hillis-Steele max-scan over the 32 chunk totals per column (smem),
//   apply exclusive carry, 32 coalesced stores. Single pass over memory.

#define H_DIM 1024
#define W_DIM 1024
#define COLS_PER_BLOCK 32
#define ROWS_PER_THREAD 32
#define CHUNKS 32  // H_DIM / ROWS_PER_THREAD

__global__ __launch_bounds__(1024, 1)
void cummax_kernel(const float* __restrict__ x, float* __restrict__ out, long long total_cols) {
    const int tid   = threadIdx.x;
    const int col_l = tid & (COLS_PER_BLOCK - 1);   // 0..31
    const int chunk = tid >> 5;                     // 0..31

    const long long col = (long long)blockIdx.x * COLS_PER_BLOCK + col_l;
    if (col >= total_cols) return;

    // col = b*W + w ; element (b,h,w) at b*H*W + h*W + w = col's base + h*W
    // since base(b,w) = b*H*W + w and col/W = b, col%W = w:
    const long long b = col >> 10;          // col / 1024
    const long long w = col & 1023;         // col % 1024
    const float* __restrict__ src = x   + b * (long long)(H_DIM * W_DIM) + w
                                        + (long long)chunk * ROWS_PER_THREAD * W_DIM;
    float* __restrict__ dst       = out + b * (long long)(H_DIM * W_DIM) + w
                                        + (long long)chunk * ROWS_PER_THREAD * W_DIM;

    // Load 32 rows (coalesced across the warp: lanes cover 32 consecutive w).
    float v[ROWS_PER_THREAD];
#pragma unroll
    for (int i = 0; i < ROWS_PER_THREAD; i++) {
        v[i] = src[(long long)i * W_DIM];
    }

    // Local inclusive prefix max within the chunk.
#pragma unroll
    for (int i = 1; i < ROWS_PER_THREAD; i++) {
        v[i] = fmaxf(v[i], v[i - 1]);
    }

    // Block-level inclusive max-scan over chunk totals, per column.
    __shared__ float s[CHUNKS][COLS_PER_BLOCK];
    float t = v[ROWS_PER_THREAD - 1];
    s[chunk][col_l] = t;
    __syncthreads();

#pragma unroll
    for (int d = 1; d < CHUNKS; d <<= 1) {
        float o = (chunk >= d) ? s[chunk - d][col_l] : -CUDART_INF_F;
        __syncthreads();
        t = fmaxf(t, o);
        s[chunk][col_l] = t;
        __syncthreads();
    }

    // Exclusive carry from all preceding chunks.
    const float carry = (chunk > 0) ? s[chunk - 1][col_l] : -CUDART_INF_F;

    // Apply carry and store (coalesced).
#pragma unroll
    for (int i = 0; i < ROWS_PER_THREAD; i++) {
        dst[(long long)i * W_DIM] = fmaxf(v[i], carry);
    }
}

extern "C" void kernel_launch(void* const* d_in, const int* in_sizes, int n_in,
                              void* d_out, int out_size) {
    const float* x = (const float*)d_in[0];
    float* out = (float*)d_out;

    const long long total_cols = 32LL * 1024LL;           // B * W
    const int grid = (int)((total_cols + COLS_PER_BLOCK - 1) / COLS_PER_BLOCK);  // 1024
    cummax_kernel<<<grid, 1024>>>(x, out, total_cols);
}